// round 14
// baseline (speedup 1.0000x reference)
#include <cuda_runtime.h>
#include <cuda_fp16.h>
#include <cstdint>

// ============================================================================
// ContrastiveLoss, single-pass fp16 mma.sync GEMM, upper triangle only.
// R14: ONE fused persistent kernel (148 CTAs = one wave, 1 CTA/SM):
//   phase1 convert (each CTA 1/148 of the fp16 plane)
//   grid barrier (replay-safe: per-barrier counter, atomicInc wrap, spin->0)
//   phase2 main MMA loop (R8 body verbatim — at the legacy-HMMA issue floor,
//          rt~24cyc/m16n8k16/SMSP; overlap tricks proven neutral in R9-R13)
//   grid barrier, phase3 finalize (56 rows/CTA) + last-CTA mean reduction.
// Deterministic: per-tile slot writes unique, fixed-order reductions.
// ============================================================================

#define N_ROWS 8192
#define DIM    128
#define BM     128
#define BN     128
#define NBLK   64
#define TOTTILES 2080        // NBLK*(NBLK+1)/2
#define NCTA   148
#define THREADS 256
#define PLANE  32768         // one 128x128 fp16 plane
#define CONV_UNITS 131072    // 8-element convert units
#define UNITS_PER_CTA 886    // ceil(131072/148)

#define SQRT_SCALE 4.53981642f   // sqrt(log2(e)/0.07)

// ---------------------------------------------------------------------------
__device__ float2 g_rpart[NBLK][N_ROWS];   // tile (i,j): rows -> [j][i*128+r]
__device__ float2 g_cpart[NBLK][N_ROWS];   // tile (i,j): cols -> [i][j*128+c]
__device__ float g_fpart[2][NCTA];
__device__ unsigned int g_ctr = 0;         // last-CTA flag (wraps each launch)
__device__ unsigned int g_barA = 0;        // grid barrier 1 (wraps each launch)
__device__ unsigned int g_barB = 0;        // grid barrier 2 (wraps each launch)
__device__ __align__(16) __half g_hi[N_ROWS * DIM];

// ---------------------------------------------------------------------------
__device__ __forceinline__ uint32_t smem_u32(const void* p) {
    uint32_t a;
    asm("{ .reg .u64 t; cvta.to.shared.u64 t, %1; cvt.u32.u64 %0, t; }"
        : "=r"(a) : "l"(p));
    return a;
}

__device__ __forceinline__ float ex2f(float x) {
    float y;
    asm("ex2.approx.ftz.f32 %0, %1;" : "=f"(y) : "f"(x));
    return y;
}

__device__ __forceinline__ void cp16(uint32_t dst, const void* src) {
    asm volatile("cp.async.cg.shared.global [%0], [%1], 16;"
                 :: "r"(dst), "l"(src) : "memory");
}
#define CP_COMMIT() asm volatile("cp.async.commit_group;" ::: "memory")
#define CP_WAIT0()  asm volatile("cp.async.wait_group 0;" ::: "memory")
#define CP_WAIT1()  asm volatile("cp.async.wait_group 1;" ::: "memory")

__device__ __forceinline__ void ldsm4(uint32_t& r0, uint32_t& r1,
                                      uint32_t& r2, uint32_t& r3, uint32_t a) {
    asm volatile("ldmatrix.sync.aligned.m8n8.x4.shared.b16 {%0,%1,%2,%3}, [%4];"
                 : "=r"(r0), "=r"(r1), "=r"(r2), "=r"(r3) : "r"(a));
}

__device__ __forceinline__ void mma16816(float& d0, float& d1, float& d2, float& d3,
                                         uint32_t a0, uint32_t a1, uint32_t a2, uint32_t a3,
                                         uint32_t b0, uint32_t b1) {
    asm volatile(
        "mma.sync.aligned.m16n8k16.row.col.f32.f16.f16.f32 "
        "{%0,%1,%2,%3}, {%4,%5,%6,%7}, {%8,%9}, {%0,%1,%2,%3};"
        : "+f"(d0), "+f"(d1), "+f"(d2), "+f"(d3)
        : "r"(a0), "r"(a1), "r"(a2), "r"(a3), "r"(b0), "r"(b1));
}

__device__ __forceinline__ int get_label(const void* p, int i, int is64) {
    if (is64) return (int)(((const long long*)p)[i]);
    return ((const int*)p)[i];
}

__device__ __forceinline__ int strip_start(int i) { return i * 64 - (i * (i - 1)) / 2; }
__device__ __forceinline__ void decode_tile(int f, int& i, int& j) {
    int s = 0;
    while (s < 63 && strip_start(s + 1) <= f) s++;
    i = s;
    j = s + (f - strip_start(s));
}
__device__ __forceinline__ void step_tile(int& i, int& j) {
    j++;
    if (j == 64) { i++; j = i; }
}

__device__ __forceinline__ uint32_t tile_addr(uint32_t base, int row, int c16) {
    return base + (uint32_t)row * 256u + (uint32_t)(((c16 ^ (row & 7)) << 4));
}

// Replay-safe grid barrier: dedicated counter per barrier, used once/launch.
// atomicInc wraps to 0 on the NCTA-th arrival; waiters spin until 0.
__device__ __forceinline__ void grid_barrier(unsigned int* ctr) {
    __syncthreads();
    if (threadIdx.x == 0) {
        __threadfence();
        atomicInc(ctr, NCTA - 1u);            // 148th arrival wraps to 0
        while (atomicAdd(ctr, 0u) != 0u) { }  // spin until all arrived
        __threadfence();
    }
    __syncthreads();
}

// ---------------------------------------------------------------------------
extern __shared__ __align__(16) char smem_dyn_c[];

__device__ __forceinline__ void stage_tile(uint32_t base, int grow0, int tid) {
    #pragma unroll
    for (int i = 0; i < 8; i++) {
        int f = tid + i * THREADS;
        int row = f >> 4;
        int c16 = f & 15;
        cp16(tile_addr(base, row, c16), g_hi + (size_t)(grow0 + row) * DIM + c16 * 8);
    }
}

__global__ void __launch_bounds__(THREADS, 1)
contrastive_fused_kernel(const float* __restrict__ emb,
                         const void* __restrict__ labels_raw,
                         float* __restrict__ out)
{
    __shared__ int s_cl[2][BN];
    __shared__ int s_flag;
    __shared__ float2 s_rr[BM][4];
    __shared__ float2 s_cr[BN][2];
    __shared__ float ws[8], wc[8];
    __shared__ int s_last;

    const int tid = threadIdx.x;
    const int lane = tid & 31;
    const int wid = tid >> 5;
    const int c = blockIdx.x;

    uint32_t sbase = (smem_u32(smem_dyn_c) + 1023u) & ~1023u;
    const uint32_t Abase = sbase;
    const uint32_t Bbuf0 = sbase + 1u * PLANE;
    const uint32_t Bbuf1 = sbase + 2u * PLANE;

    if (tid == 0) {
        const int* li = (const int*)labels_raw;
        int is64 = 1;
        for (int i = 0; i < 64; i++)
            if (li[2 * i + 1] != 0) { is64 = 0; break; }
        s_flag = is64;
    }
    __syncthreads();
    const int is64 = s_flag;

    // ===================== phase 1: convert =====================
    {
        const int u0 = c * UNITS_PER_CTA;
        const int u1 = (u0 + UNITS_PER_CTA < CONV_UNITS) ? u0 + UNITS_PER_CTA : CONV_UNITS;
        for (int u = u0 + tid; u < u1; u += THREADS) {
            int r = u >> 4;
            int c8 = u & 15;
            const float4* src = (const float4*)(emb + (size_t)r * DIM + c8 * 8);
            float4 v0 = src[0], v1 = src[1];
            float a[8] = {v0.x, v0.y, v0.z, v0.w, v1.x, v1.y, v1.z, v1.w};
            uint32_t hi[4];
            #pragma unroll
            for (int p = 0; p < 4; p++) {
                __half h0 = __float2half_rn(a[2 * p] * SQRT_SCALE);
                __half h1 = __float2half_rn(a[2 * p + 1] * SQRT_SCALE);
                hi[p] = (uint32_t)__half_as_ushort(h0) | ((uint32_t)__half_as_ushort(h1) << 16);
            }
            *(uint4*)(g_hi + (size_t)r * DIM + c8 * 8) = make_uint4(hi[0], hi[1], hi[2], hi[3]);
        }
    }
    grid_barrier(&g_barA);

    // ===================== phase 2: main MMA loop (R8 body) =====================
    const int wm = wid >> 2;       // 0..1
    const int wn = wid & 3;        // 0..3
    const int m0 = wm * 64;
    const int n0 = wn * 32;
    const int g = lane >> 2;
    const int tig = lane & 3;

    const uint32_t aRowOff = (uint32_t)(m0 + (lane & 15)) * 256u;
    const int kh = lane >> 4;                                   // A k-half bit
    const uint32_t bRowOff = (uint32_t)(n0 + (lane & 7) + ((lane >> 4) & 1) * 8) * 256u;
    const int kb = (lane >> 3) & 1;                             // B k-half bit
    const int sx = lane & 7;                                    // swizzle xor

    const int f0 = (c * TOTTILES) / NCTA;
    const int f1 = ((c + 1) * TOTTILES) / NCTA;
    int ti, tj;
    decode_tile(f0, ti, tj);

    int rl[8];
    #pragma unroll
    for (int mc = 0; mc < 2; mc++)
        #pragma unroll
        for (int mfl = 0; mfl < 2; mfl++) {
            rl[mc * 4 + mfl * 2]     = get_label(labels_raw, ti * BM + m0 + mc * 32 + mfl * 16 + g, is64);
            rl[mc * 4 + mfl * 2 + 1] = get_label(labels_raw, ti * BM + m0 + mc * 32 + mfl * 16 + g + 8, is64);
        }

    stage_tile(Abase, ti * BM, tid);
    stage_tile(Bbuf0, tj * BN, tid);
    CP_COMMIT();
    {
        int i1 = ti, j1 = tj;
        step_tile(i1, j1);
        if (f0 + 1 < f1) stage_tile(Bbuf1, j1 * BN, tid);
        CP_COMMIT();
    }

    for (int t = f0; t < f1; ++t) {
        const int cb = (t - f0) & 1;          // LOCAL parity
        const uint32_t Bb = cb ? Bbuf1 : Bbuf0;

        if (t > f0 && tj == ti) {
            __syncthreads();                  // everyone done with old A
            stage_tile(Abase, ti * BM, tid);
            #pragma unroll
            for (int mc = 0; mc < 2; mc++)
                #pragma unroll
                for (int mfl = 0; mfl < 2; mfl++) {
                    rl[mc * 4 + mfl * 2]     = get_label(labels_raw, ti * BM + m0 + mc * 32 + mfl * 16 + g, is64);
                    rl[mc * 4 + mfl * 2 + 1] = get_label(labels_raw, ti * BM + m0 + mc * 32 + mfl * 16 + g + 8, is64);
                }
            CP_COMMIT();
            CP_WAIT0();                       // drain A + pending B
        } else {
            CP_WAIT1();                       // B(t) resident
        }

        if (tid < BN) s_cl[cb][tid] = get_label(labels_raw, tj * BN + tid, is64);
        __syncthreads();                      // B(t) + labels visible to all

        const int diag = (ti == tj);
        float rt[8], rp[8], ct[8], cp[8];
        #pragma unroll
        for (int i = 0; i < 8; i++) { rt[i] = 0.f; rp[i] = 0.f; ct[i] = 0.f; cp[i] = 0.f; }

        // two m-chunks (32x32 each): full-K MMA then immediate epilogue
        #pragma unroll
        for (int mc = 0; mc < 2; mc++) {
            const uint32_t aChunk = Abase + aRowOff + (uint32_t)(mc * 8192);

            float acc[32];
            #pragma unroll
            for (int i = 0; i < 32; i++) acc[i] = 0.f;

            #pragma unroll
            for (int ks = 0; ks < 8; ks++) {
                uint32_t ac = (uint32_t)(((2 * ks + kh) ^ sx) << 4);
                uint32_t a0, a1, a2, a3, a4, a5, a6, a7;
                ldsm4(a0, a1, a2, a3, aChunk + ac);            // rows +0..15
                ldsm4(a4, a5, a6, a7, aChunk + 4096u + ac);    // rows +16..31

                uint32_t bc = (uint32_t)(((2 * ks + kb) ^ sx) << 4);
                uint32_t b[8];
                ldsm4(b[0], b[1], b[2], b[3], Bb + bRowOff + bc);           // cols n0..+15
                ldsm4(b[4], b[5], b[6], b[7], Bb + bRowOff + 4096u + bc);   // cols +16..31

                #pragma unroll
                for (int nf = 0; nf < 4; nf++) {
                    mma16816(acc[nf * 4],     acc[nf * 4 + 1], acc[nf * 4 + 2], acc[nf * 4 + 3],
                             a0, a1, a2, a3, b[nf * 2], b[nf * 2 + 1]);
                    mma16816(acc[16 + nf * 4], acc[16 + nf * 4 + 1], acc[16 + nf * 4 + 2], acc[16 + nf * 4 + 3],
                             a4, a5, a6, a7, b[nf * 2], b[nf * 2 + 1]);
                }
            }

            #pragma unroll
            for (int nf = 0; nf < 4; nf++) {
                const int lc0 = n0 + nf * 8 + tig * 2;
                const int cl0 = s_cl[cb][lc0];
                const int cl1 = s_cl[cb][lc0 + 1];
                #pragma unroll
                for (int mfl = 0; mfl < 2; mfl++) {
                    const int d = mfl * 16 + nf * 4;
                    float e00 = ex2f(acc[d]);
                    float e01 = ex2f(acc[d + 1]);
                    float e10 = ex2f(acc[d + 2]);
                    float e11 = ex2f(acc[d + 3]);
                    if (diag) {
                        const int lr0 = m0 + mc * 32 + mfl * 16 + g;
                        const int lr1 = lr0 + 8;
                        if (lr0 == lc0)     e00 = 0.f;
                        if (lr0 == lc0 + 1) e01 = 0.f;
                        if (lr1 == lc0)     e10 = 0.f;
                        if (lr1 == lc0 + 1) e11 = 0.f;
                    }
                    const int ri = mc * 4 + mfl * 2;
                    float p00 = (cl0 == rl[ri])     ? e00 : 0.f;
                    float p01 = (cl1 == rl[ri])     ? e01 : 0.f;
                    float p10 = (cl0 == rl[ri + 1]) ? e10 : 0.f;
                    float p11 = (cl1 == rl[ri + 1]) ? e11 : 0.f;
                    rt[ri]     += e00 + e01;
                    rt[ri + 1] += e10 + e11;
                    rp[ri]     += p00 + p01;
                    rp[ri + 1] += p10 + p11;
                    ct[nf * 2]     += e00 + e10;
                    ct[nf * 2 + 1] += e01 + e11;
                    cp[nf * 2]     += p00 + p10;
                    cp[nf * 2 + 1] += p01 + p11;
                }
            }
        }

        __syncthreads();                      // all warps done reading Bb
        {
            int i2 = ti, j2 = tj;
            step_tile(i2, j2);
            step_tile(i2, j2);
            if (t + 2 < f1) stage_tile(Bb, j2 * BN, tid);
            CP_COMMIT();
        }

        #pragma unroll
        for (int i = 0; i < 8; i++) {         // rows: reduce over tig
            rt[i] += __shfl_xor_sync(0xFFFFFFFFu, rt[i], 1);
            rt[i] += __shfl_xor_sync(0xFFFFFFFFu, rt[i], 2);
            rp[i] += __shfl_xor_sync(0xFFFFFFFFu, rp[i], 1);
            rp[i] += __shfl_xor_sync(0xFFFFFFFFu, rp[i], 2);
        }
        #pragma unroll
        for (int i = 0; i < 8; i++) {         // cols: reduce over g
            ct[i] += __shfl_xor_sync(0xFFFFFFFFu, ct[i], 4);
            ct[i] += __shfl_xor_sync(0xFFFFFFFFu, ct[i], 8);
            ct[i] += __shfl_xor_sync(0xFFFFFFFFu, ct[i], 16);
            cp[i] += __shfl_xor_sync(0xFFFFFFFFu, cp[i], 4);
            cp[i] += __shfl_xor_sync(0xFFFFFFFFu, cp[i], 8);
            cp[i] += __shfl_xor_sync(0xFFFFFFFFu, cp[i], 16);
        }
        if (tig == 0) {
            #pragma unroll
            for (int mc = 0; mc < 2; mc++)
                #pragma unroll
                for (int mfl = 0; mfl < 2; mfl++) {
                    const int ri = mc * 4 + mfl * 2;
                    const int row = m0 + mc * 32 + mfl * 16 + g;
                    s_rr[row][wn]     = make_float2(rt[ri],     rp[ri]);
                    s_rr[row + 8][wn] = make_float2(rt[ri + 1], rp[ri + 1]);
                }
        }
        if (lane < 4) {
            #pragma unroll
            for (int nf = 0; nf < 4; nf++) {
                const int col = n0 + nf * 8 + lane * 2;
                s_cr[col][wm]     = make_float2(ct[nf * 2],     cp[nf * 2]);
                s_cr[col + 1][wm] = make_float2(ct[nf * 2 + 1], cp[nf * 2 + 1]);
            }
        }
        __syncthreads();
        if (tid < BM) {
            float2 a0 = s_rr[tid][0], a1 = s_rr[tid][1], a2 = s_rr[tid][2], a3 = s_rr[tid][3];
            g_rpart[tj][ti * BM + tid] =
                make_float2(a0.x + a1.x + a2.x + a3.x, a0.y + a1.y + a2.y + a3.y);
        } else {
            const int cc = tid - BM;
            float2 a0 = s_cr[cc][0], a1 = s_cr[cc][1];
            g_cpart[ti][tj * BN + cc] = make_float2(a0.x + a1.x, a0.y + a1.y);
        }

        step_tile(ti, tj);
    }

    // ===================== phase 3: finalize =====================
    grid_barrier(&g_barB);

    {
        float loss = 0.f, cnt = 0.f;
        const int r = c * 56 + tid;           // 148*56 = 8288 >= 8192
        if (tid < 56 && r < N_ROWS) {
            const int b = r >> 7;
            float tt = 0.f, pp = 0.f;
            for (int j = b; j < NBLK; j++) {
                float2 v = g_rpart[j][r];
                tt += v.x; pp += v.y;
            }
            for (int i = 0; i < b; i++) {
                float2 v = g_cpart[i][r];
                tt += v.x; pp += v.y;
            }
            if (pp > 0.f) {
                loss = -logf(pp / (tt + 1e-8f) + 1e-8f);
                cnt = 1.f;
            }
        }
        #pragma unroll
        for (int o = 16; o > 0; o >>= 1) {
            loss += __shfl_xor_sync(0xFFFFFFFFu, loss, o);
            cnt  += __shfl_xor_sync(0xFFFFFFFFu, cnt, o);
        }
        if (lane == 0) { ws[wid] = loss; wc[wid] = cnt; }
        __syncthreads();
        if (tid == 0) {
            float S = 0.f, C = 0.f;
            #pragma unroll
            for (int w = 0; w < 8; w++) { S += ws[w]; C += wc[w]; }
            g_fpart[0][c] = S;
            g_fpart[1][c] = C;
            __threadfence();
            unsigned int v = atomicInc(&g_ctr, NCTA - 1u);  // wraps to 0 on last
            s_last = (v == NCTA - 1u);
        }
        __syncthreads();
        if (s_last) {
            float S = 0.f, C = 0.f;
            if (tid < NCTA) { S = g_fpart[0][tid]; C = g_fpart[1][tid]; }
            #pragma unroll
            for (int o = 16; o > 0; o >>= 1) {
                S += __shfl_xor_sync(0xFFFFFFFFu, S, o);
                C += __shfl_xor_sync(0xFFFFFFFFu, C, o);
            }
            if (lane == 0) { ws[wid] = S; wc[wid] = C; }
            __syncthreads();
            if (tid == 0) {
                float SS = 0.f, CC = 0.f;
                #pragma unroll
                for (int w = 0; w < 8; w++) { SS += ws[w]; CC += wc[w]; }
                out[0] = (CC > 0.f) ? SS / fmaxf(CC, 1.f) : 0.f;
            }
        }
    }
}

// ---------------------------------------------------------------------------
extern "C" void kernel_launch(void* const* d_in, const int* in_sizes, int n_in,
                              void* d_out, int out_size)
{
    const float* emb = (const float*)d_in[0];
    const void* labels = d_in[1];
    float* out = (float*)d_out;

    const int dyn_smem = 1024 + 3 * PLANE;   // pad + A + 2x B
    cudaFuncSetAttribute(contrastive_fused_kernel,
                         cudaFuncAttributeMaxDynamicSharedMemorySize, dyn_smem);

    contrastive_fused_kernel<<<NCTA, THREADS, dyn_smem>>>(emb, labels, out);
}

// round 15
// speedup vs baseline: 1.1231x; 1.1231x over previous
#include <cuda_runtime.h>
#include <cuda_fp16.h>
#include <cstdint>

// ============================================================================
// ContrastiveLoss, single-pass fp16 mma.sync GEMM, upper triangle only.
// R15 = R11 (2 CTAs/SM, NCTA=296) with a REGISTER-LEAN tile body:
// R14's profile showed tensor=25.7%, issue=28%, occ=12.6% -> latency-bound,
// and R11's launch_bounds(256,2) had silently spilled (~197 regs capped to
// 128). Per-chunk row tails + only ct/cp live across chunks -> ~90 regs peak,
// so two CTAs actually run at full speed and interleave their stall phases.
// Deterministic: per-tile slot writes unique, fixed-order reductions.
// ============================================================================

#define N_ROWS 8192
#define DIM    128
#define BM     128
#define BN     128
#define NBLK   64
#define TOTTILES 2080        // NBLK*(NBLK+1)/2
#define NCTA   296           // 2 CTAs per SM
#define THREADS 256
#define PLANE  32768         // one 128x128 fp16 plane

#define SQRT_SCALE 4.53981642f   // sqrt(log2(e)/0.07)

// ---------------------------------------------------------------------------
__device__ float2 g_rpart[NBLK][N_ROWS];   // tile (i,j): rows -> [j][i*128+r]
__device__ float2 g_cpart[NBLK][N_ROWS];   // tile (i,j): cols -> [i][j*128+c]
__device__ float g_fpart[2][32];
__device__ unsigned int g_ctr = 0;
__device__ __align__(16) __half g_hi[N_ROWS * DIM];

// ---------------------------------------------------------------------------
__device__ __forceinline__ uint32_t smem_u32(const void* p) {
    uint32_t a;
    asm("{ .reg .u64 t; cvta.to.shared.u64 t, %1; cvt.u32.u64 %0, t; }"
        : "=r"(a) : "l"(p));
    return a;
}

__device__ __forceinline__ float ex2f(float x) {
    float y;
    asm("ex2.approx.ftz.f32 %0, %1;" : "=f"(y) : "f"(x));
    return y;
}

__device__ __forceinline__ void cp16(uint32_t dst, const void* src) {
    asm volatile("cp.async.cg.shared.global [%0], [%1], 16;"
                 :: "r"(dst), "l"(src) : "memory");
}
#define CP_COMMIT() asm volatile("cp.async.commit_group;" ::: "memory")
#define CP_WAIT0()  asm volatile("cp.async.wait_group 0;" ::: "memory")
#define CP_WAIT1()  asm volatile("cp.async.wait_group 1;" ::: "memory")

__device__ __forceinline__ void ldsm4(uint32_t& r0, uint32_t& r1,
                                      uint32_t& r2, uint32_t& r3, uint32_t a) {
    asm volatile("ldmatrix.sync.aligned.m8n8.x4.shared.b16 {%0,%1,%2,%3}, [%4];"
                 : "=r"(r0), "=r"(r1), "=r"(r2), "=r"(r3) : "r"(a));
}

__device__ __forceinline__ void mma16816(float& d0, float& d1, float& d2, float& d3,
                                         uint32_t a0, uint32_t a1, uint32_t a2, uint32_t a3,
                                         uint32_t b0, uint32_t b1) {
    asm volatile(
        "mma.sync.aligned.m16n8k16.row.col.f32.f16.f16.f32 "
        "{%0,%1,%2,%3}, {%4,%5,%6,%7}, {%8,%9}, {%0,%1,%2,%3};"
        : "+f"(d0), "+f"(d1), "+f"(d2), "+f"(d3)
        : "r"(a0), "r"(a1), "r"(a2), "r"(a3), "r"(b0), "r"(b1));
}

__device__ __forceinline__ int get_label(const void* p, int i, int is64) {
    if (is64) return (int)(((const long long*)p)[i]);
    return ((const int*)p)[i];
}

__device__ __forceinline__ int strip_start(int i) { return i * 64 - (i * (i - 1)) / 2; }
__device__ __forceinline__ void decode_tile(int f, int& i, int& j) {
    int s = 0;
    while (s < 63 && strip_start(s + 1) <= f) s++;
    i = s;
    j = s + (f - strip_start(s));
}
__device__ __forceinline__ void step_tile(int& i, int& j) {
    j++;
    if (j == 64) { i++; j = i; }
}

__device__ __forceinline__ uint32_t tile_addr(uint32_t base, int row, int c16) {
    return base + (uint32_t)row * 256u + (uint32_t)(((c16 ^ (row & 7)) << 4));
}

// ---------------------------------------------------------------------------
// convert: fp32 emb -> prescaled fp16, row-major
// ---------------------------------------------------------------------------
__global__ void __launch_bounds__(256)
convert_kernel(const float* __restrict__ emb)
{
    int f = blockIdx.x * 256 + threadIdx.x;
    int r = f >> 4;
    int c8 = f & 15;
    const float4* src = (const float4*)(emb + (size_t)r * DIM + c8 * 8);
    float4 v0 = src[0], v1 = src[1];
    float a[8] = {v0.x, v0.y, v0.z, v0.w, v1.x, v1.y, v1.z, v1.w};

    uint32_t hi[4];
    #pragma unroll
    for (int p = 0; p < 4; p++) {
        __half h0 = __float2half_rn(a[2 * p] * SQRT_SCALE);
        __half h1 = __float2half_rn(a[2 * p + 1] * SQRT_SCALE);
        hi[p] = (uint32_t)__half_as_ushort(h0) | ((uint32_t)__half_as_ushort(h1) << 16);
    }
    *(uint4*)(g_hi + (size_t)r * DIM + c8 * 8) = make_uint4(hi[0], hi[1], hi[2], hi[3]);
}

// ---------------------------------------------------------------------------
// main MMA kernel
// ---------------------------------------------------------------------------
extern __shared__ __align__(16) char smem_dyn_c[];

__device__ __forceinline__ void stage_tile(uint32_t base, int grow0, int tid) {
    #pragma unroll
    for (int i = 0; i < 8; i++) {
        int f = tid + i * THREADS;
        int row = f >> 4;
        int c16 = f & 15;
        cp16(tile_addr(base, row, c16), g_hi + (size_t)(grow0 + row) * DIM + c16 * 8);
    }
}

__global__ void __launch_bounds__(THREADS, 2)
contrastive_mma_kernel(const void* __restrict__ labels_raw)
{
    __shared__ int s_cl[2][BN];
    __shared__ int s_flag;
    __shared__ float2 s_rr[BM][4];
    __shared__ float2 s_cr[BN][2];

    const int tid = threadIdx.x;
    const int lane = tid & 31;
    const int wid = tid >> 5;
    const int c = blockIdx.x;

    uint32_t sbase = (smem_u32(smem_dyn_c) + 1023u) & ~1023u;
    const uint32_t Abase = sbase;
    const uint32_t Bbuf0 = sbase + 1u * PLANE;
    const uint32_t Bbuf1 = sbase + 2u * PLANE;

    if (tid == 0) {
        const int* li = (const int*)labels_raw;
        int is64 = 1;
        for (int i = 0; i < 64; i++)
            if (li[2 * i + 1] != 0) { is64 = 0; break; }
        s_flag = is64;
    }
    __syncthreads();
    const int is64 = s_flag;

    const int wm = wid >> 2;       // 0..1
    const int wn = wid & 3;        // 0..3
    const int m0 = wm * 64;
    const int n0 = wn * 32;
    const int g = lane >> 2;
    const int tig = lane & 3;

    // per-lane ldmatrix address components (formulas verified in R3-R14)
    const uint32_t aRowOff = (uint32_t)(m0 + (lane & 15)) * 256u;
    const int kh = lane >> 4;                                   // A k-half bit
    const uint32_t bRowOff = (uint32_t)(n0 + (lane & 7) + ((lane >> 4) & 1) * 8) * 256u;
    const int kb = (lane >> 3) & 1;                             // B k-half bit
    const int sx = lane & 7;                                    // swizzle xor

    const int f0 = (c * TOTTILES) / NCTA;
    const int f1 = ((c + 1) * TOTTILES) / NCTA;
    int ti, tj;
    decode_tile(f0, ti, tj);

    // row labels: rows m0 + mc*32 + mfl*16 + g (+8), index mc*4 + mfl*2 + {0,1}
    int rl[8];
    #pragma unroll
    for (int mc = 0; mc < 2; mc++)
        #pragma unroll
        for (int mfl = 0; mfl < 2; mfl++) {
            rl[mc * 4 + mfl * 2]     = get_label(labels_raw, ti * BM + m0 + mc * 32 + mfl * 16 + g, is64);
            rl[mc * 4 + mfl * 2 + 1] = get_label(labels_raw, ti * BM + m0 + mc * 32 + mfl * 16 + g + 8, is64);
        }

    // prologue: A + B(f0) -> group 0; B(f0+1) -> group 1
    stage_tile(Abase, ti * BM, tid);
    stage_tile(Bbuf0, tj * BN, tid);
    CP_COMMIT();
    {
        int i1 = ti, j1 = tj;
        step_tile(i1, j1);
        if (f0 + 1 < f1) stage_tile(Bbuf1, j1 * BN, tid);
        CP_COMMIT();
    }

    for (int t = f0; t < f1; ++t) {
        const int cb = (t - f0) & 1;          // LOCAL parity
        const uint32_t Bb = cb ? Bbuf1 : Bbuf0;

        if (t > f0 && tj == ti) {
            __syncthreads();                  // everyone done with old A
            stage_tile(Abase, ti * BM, tid);
            #pragma unroll
            for (int mc = 0; mc < 2; mc++)
                #pragma unroll
                for (int mfl = 0; mfl < 2; mfl++) {
                    rl[mc * 4 + mfl * 2]     = get_label(labels_raw, ti * BM + m0 + mc * 32 + mfl * 16 + g, is64);
                    rl[mc * 4 + mfl * 2 + 1] = get_label(labels_raw, ti * BM + m0 + mc * 32 + mfl * 16 + g + 8, is64);
                }
            CP_COMMIT();
            CP_WAIT0();                       // drain A + pending B
        } else {
            CP_WAIT1();                       // B(t) resident
        }

        if (tid < BN) s_cl[cb][tid] = get_label(labels_raw, tj * BN + tid, is64);
        __syncthreads();                      // B(t) + labels visible to all

        const int diag = (ti == tj);
        float ct[8], cp[8];                   // col sums live across both chunks
        #pragma unroll
        for (int i = 0; i < 8; i++) { ct[i] = 0.f; cp[i] = 0.f; }

        // two m-chunks (32x32 each): MMA + epilogue + per-chunk ROW tail
        #pragma unroll
        for (int mc = 0; mc < 2; mc++) {
            const uint32_t aChunk = Abase + aRowOff + (uint32_t)(mc * 8192);

            float acc[32];
            #pragma unroll
            for (int i = 0; i < 32; i++) acc[i] = 0.f;

            #pragma unroll
            for (int ks = 0; ks < 8; ks++) {
                uint32_t ac = (uint32_t)(((2 * ks + kh) ^ sx) << 4);
                uint32_t a0, a1, a2, a3, a4, a5, a6, a7;
                ldsm4(a0, a1, a2, a3, aChunk + ac);            // rows +0..15
                ldsm4(a4, a5, a6, a7, aChunk + 4096u + ac);    // rows +16..31

                uint32_t bc = (uint32_t)(((2 * ks + kb) ^ sx) << 4);
                uint32_t b[8];
                ldsm4(b[0], b[1], b[2], b[3], Bb + bRowOff + bc);           // cols n0..+15
                ldsm4(b[4], b[5], b[6], b[7], Bb + bRowOff + 4096u + bc);   // cols +16..31

                #pragma unroll
                for (int nf = 0; nf < 4; nf++) {
                    mma16816(acc[nf * 4],     acc[nf * 4 + 1], acc[nf * 4 + 2], acc[nf * 4 + 3],
                             a0, a1, a2, a3, b[nf * 2], b[nf * 2 + 1]);
                    mma16816(acc[16 + nf * 4], acc[16 + nf * 4 + 1], acc[16 + nf * 4 + 2], acc[16 + nf * 4 + 3],
                             a4, a5, a6, a7, b[nf * 2], b[nf * 2 + 1]);
                }
            }

            float rt[4], rp[4];               // chunk-local row sums
            #pragma unroll
            for (int i = 0; i < 4; i++) { rt[i] = 0.f; rp[i] = 0.f; }

            #pragma unroll
            for (int nf = 0; nf < 4; nf++) {
                const int lc0 = n0 + nf * 8 + tig * 2;
                const int cl0 = s_cl[cb][lc0];
                const int cl1 = s_cl[cb][lc0 + 1];
                #pragma unroll
                for (int mfl = 0; mfl < 2; mfl++) {
                    const int d = mfl * 16 + nf * 4;
                    float e00 = ex2f(acc[d]);
                    float e01 = ex2f(acc[d + 1]);
                    float e10 = ex2f(acc[d + 2]);
                    float e11 = ex2f(acc[d + 3]);
                    if (diag) {
                        const int lr0 = m0 + mc * 32 + mfl * 16 + g;
                        const int lr1 = lr0 + 8;
                        if (lr0 == lc0)     e00 = 0.f;
                        if (lr0 == lc0 + 1) e01 = 0.f;
                        if (lr1 == lc0)     e10 = 0.f;
                        if (lr1 == lc0 + 1) e11 = 0.f;
                    }
                    const int rg = mc * 4 + mfl * 2;   // global rl index
                    const int rc = mfl * 2;            // chunk-local sum index
                    float p00 = (cl0 == rl[rg])     ? e00 : 0.f;
                    float p01 = (cl1 == rl[rg])     ? e01 : 0.f;
                    float p10 = (cl0 == rl[rg + 1]) ? e10 : 0.f;
                    float p11 = (cl1 == rl[rg + 1]) ? e11 : 0.f;
                    rt[rc]     += e00 + e01;
                    rt[rc + 1] += e10 + e11;
                    rp[rc]     += p00 + p01;
                    rp[rc + 1] += p10 + p11;
                    ct[nf * 2]     += e00 + e10;
                    ct[nf * 2 + 1] += e01 + e11;
                    cp[nf * 2]     += p00 + p10;
                    cp[nf * 2 + 1] += p01 + p11;
                }
            }

            // per-chunk row tail: reduce over tig, write this chunk's rows
            #pragma unroll
            for (int i = 0; i < 4; i++) {
                rt[i] += __shfl_xor_sync(0xFFFFFFFFu, rt[i], 1);
                rt[i] += __shfl_xor_sync(0xFFFFFFFFu, rt[i], 2);
                rp[i] += __shfl_xor_sync(0xFFFFFFFFu, rp[i], 1);
                rp[i] += __shfl_xor_sync(0xFFFFFFFFu, rp[i], 2);
            }
            if (tig == 0) {
                #pragma unroll
                for (int mfl = 0; mfl < 2; mfl++) {
                    const int row = m0 + mc * 32 + mfl * 16 + g;
                    s_rr[row][wn]     = make_float2(rt[mfl * 2],     rp[mfl * 2]);
                    s_rr[row + 8][wn] = make_float2(rt[mfl * 2 + 1], rp[mfl * 2 + 1]);
                }
            }
        }

        __syncthreads();                      // all warps done reading Bb
        {                                     // prefetch B(t+2) into freed buffer
            int i2 = ti, j2 = tj;
            step_tile(i2, j2);
            step_tile(i2, j2);
            if (t + 2 < f1) stage_tile(Bb, j2 * BN, tid);
            CP_COMMIT();
        }

        // col tail: reduce over g, write s_cr
        #pragma unroll
        for (int i = 0; i < 8; i++) {
            ct[i] += __shfl_xor_sync(0xFFFFFFFFu, ct[i], 4);
            ct[i] += __shfl_xor_sync(0xFFFFFFFFu, ct[i], 8);
            ct[i] += __shfl_xor_sync(0xFFFFFFFFu, ct[i], 16);
            cp[i] += __shfl_xor_sync(0xFFFFFFFFu, cp[i], 4);
            cp[i] += __shfl_xor_sync(0xFFFFFFFFu, cp[i], 8);
            cp[i] += __shfl_xor_sync(0xFFFFFFFFu, cp[i], 16);
        }
        if (lane < 4) {
            #pragma unroll
            for (int nf = 0; nf < 4; nf++) {
                const int col = n0 + nf * 8 + lane * 2;
                s_cr[col][wm]     = make_float2(ct[nf * 2],     cp[nf * 2]);
                s_cr[col + 1][wm] = make_float2(ct[nf * 2 + 1], cp[nf * 2 + 1]);
            }
        }
        __syncthreads();
        if (tid < BM) {
            float2 a0 = s_rr[tid][0], a1 = s_rr[tid][1], a2 = s_rr[tid][2], a3 = s_rr[tid][3];
            g_rpart[tj][ti * BM + tid] =
                make_float2(a0.x + a1.x + a2.x + a3.x, a0.y + a1.y + a2.y + a3.y);
        } else {
            const int cc = tid - BM;
            float2 a0 = s_cr[cc][0], a1 = s_cr[cc][1];
            g_cpart[ti][tj * BN + cc] = make_float2(a0.x + a1.x, a0.y + a1.y);
        }

        step_tile(ti, tj);
    }
}

// ---------------------------------------------------------------------------
// merged finalize: 32 blocks; last block reduces the 32 partials
// ---------------------------------------------------------------------------
__global__ void __launch_bounds__(256)
finalize_kernel(float* __restrict__ out)
{
    __shared__ float ws[8], wc[8];
    __shared__ int s_last;
    const int tid = threadIdx.x;
    const int r = blockIdx.x * 256 + tid;
    const int b = r >> 7;

    float tt = 0.f, pp = 0.f;
    for (int j = b; j < NBLK; j++) {
        float2 v = g_rpart[j][r];
        tt += v.x; pp += v.y;
    }
    for (int i = 0; i < b; i++) {
        float2 v = g_cpart[i][r];
        tt += v.x; pp += v.y;
    }

    float loss = 0.f, cnt = 0.f;
    if (pp > 0.f) {
        loss = -logf(pp / (tt + 1e-8f) + 1e-8f);
        cnt = 1.f;
    }
    #pragma unroll
    for (int o = 16; o > 0; o >>= 1) {
        loss += __shfl_xor_sync(0xFFFFFFFFu, loss, o);
        cnt  += __shfl_xor_sync(0xFFFFFFFFu, cnt, o);
    }
    if ((tid & 31) == 0) { ws[tid >> 5] = loss; wc[tid >> 5] = cnt; }
    __syncthreads();
    if (tid == 0) {
        float S = 0.f, C = 0.f;
        #pragma unroll
        for (int w = 0; w < 8; w++) { S += ws[w]; C += wc[w]; }
        g_fpart[0][blockIdx.x] = S;
        g_fpart[1][blockIdx.x] = C;
        __threadfence();
        unsigned int v = atomicInc(&g_ctr, 31u);   // wraps to 0 on the last block
        s_last = (v == 31u);
    }
    __syncthreads();
    if (s_last && tid < 32) {
        float S = g_fpart[0][tid];
        float C = g_fpart[1][tid];
        #pragma unroll
        for (int o = 16; o > 0; o >>= 1) {
            S += __shfl_xor_sync(0xFFFFFFFFu, S, o);
            C += __shfl_xor_sync(0xFFFFFFFFu, C, o);
        }
        if (tid == 0) out[0] = (C > 0.f) ? S / fmaxf(C, 1.f) : 0.f;
    }
}

// ---------------------------------------------------------------------------
extern "C" void kernel_launch(void* const* d_in, const int* in_sizes, int n_in,
                              void* d_out, int out_size)
{
    const float* emb = (const float*)d_in[0];
    const void* labels = d_in[1];
    float* out = (float*)d_out;

    const int dyn_smem = 1024 + 3 * PLANE;   // pad + A + 2x B
    cudaFuncSetAttribute(contrastive_mma_kernel,
                         cudaFuncAttributeMaxDynamicSharedMemorySize, dyn_smem);

    convert_kernel<<<512, 256>>>(emb);
    contrastive_mma_kernel<<<NCTA, THREADS, dyn_smem>>>(labels);
    finalize_kernel<<<32, 256>>>(out);
}